// round 16
// baseline (speedup 1.0000x reference)
#include <cuda_runtime.h>
#include <stdint.h>

#define CC   128
#define CI   32
#define HH   128
#define WW   256
#define BB   8
#define HW   (HH*WW)

// Precomputed parameters (filled by prep kernel each launch; deterministic).
__device__ uint32_t g_w1m[CI][4];
__device__ int      g_pthr1[CI];        // conv1: bit set  <=>  pc <= pthr1
__device__ uint32_t g_w2m[CI][9];
__device__ int      g_sthr2[CI];        // conv2 interior: bit <=> popc-sum <= sthr2
__device__ int      g_zthr2[CI];        // conv2 border:   bit <=> z >= zthr2
__device__ uint32_t g_w3m[CC];
__device__ float    g_tab3[CC * 33];    // tab3[c*33+p] = prelu_a3(bn3(32-2p))

// Scratch: h1 binarized activations, 32 channels packed per pixel. 1 MB.
__device__ uint32_t g_h1b[BB * HW];

// ---------------------------------------------------------------------------
// Prep: ballots one word per warp (544 words over 68 blocks x 8 warps);
// block 0 additionally computes integer sign-thresholds (exact: scans every
// reachable integer z with the same float ops the reference uses — bn is
// monotone since inv = g/sqrt(v+eps) > 0) and the conv3 epilogue LUT.
// ---------------------------------------------------------------------------
__global__ void __launch_bounds__(256) prep_kernel(
    const float* __restrict__ w1, const float* __restrict__ g1,
    const float* __restrict__ b1, const float* __restrict__ m1, const float* __restrict__ v1,
    const float* __restrict__ w2, const float* __restrict__ g2,
    const float* __restrict__ b2, const float* __restrict__ m2, const float* __restrict__ v2,
    const float* __restrict__ w3, const float* __restrict__ g3,
    const float* __restrict__ b3, const float* __restrict__ m3, const float* __restrict__ v3,
    const float* __restrict__ a3p)
{
    int tid  = threadIdx.x;
    int lane = tid & 31;
    int gw   = blockIdx.x * 8 + (tid >> 5);   // global word id 0..543

    if (gw < 128) {
        int oc = gw >> 2, j = gw & 3;
        uint32_t m = __ballot_sync(0xffffffffu, w1[oc * CC + j * 32 + lane] > 0.f);
        if (lane == 0) g_w1m[oc][j] = m;
    } else if (gw < 416) {
        int idx = gw - 128;
        int oc = idx / 9, t9 = idx - oc * 9;
        uint32_t m = __ballot_sync(0xffffffffu, w2[oc * (CI * 9) + lane * 9 + t9] > 0.f);
        if (lane == 0) g_w2m[oc][t9] = m;
    } else if (gw < 544) {
        int c = gw - 416;
        uint32_t m = __ballot_sync(0xffffffffu, w3[c * CI + lane] > 0.f);
        if (lane == 0) g_w3m[c] = m;
    }

    if (blockIdx.x == 0) {
        if (tid < CI) {
            // conv1 threshold: z = 128-2pc decreasing in pc -> positives are a
            // prefix in pc. pthr1 = max pc with bn1(z) > 0 (or -1).
            float inv = __fdiv_rn(g1[tid], __fsqrt_rn(__fadd_rn(v1[tid], 1e-5f)));
            float bb  = __fadd_rn(b1[tid], -__fmul_rn(m1[tid], inv));
            int thr = -1;
            for (int pc = 0; pc <= 128; pc++) {
                float v = __fadd_rn(__fmul_rn((float)(128 - 2 * pc), inv), bb);
                if (v > 0.f) thr = pc;
            }
            g_pthr1[tid] = thr;
        } else if (tid >= 64 && tid < 64 + CI) {
            // conv2 threshold: bn2(z) increasing in z -> positives are a
            // suffix. zthr2 = min z in [-288,288] with bn2(z) > 0 (289 = never).
            int t = tid - 64;
            float inv = __fdiv_rn(g2[t], __fsqrt_rn(__fadd_rn(v2[t], 1e-5f)));
            float bb  = __fadd_rn(b2[t], -__fmul_rn(m2[t], inv));
            int zthr = 289;
            for (int z = 288; z >= -288; z--) {
                float v = __fadd_rn(__fmul_rn((float)z, inv), bb);
                if (v > 0.f) zthr = z; else break;
            }
            g_zthr2[t] = zthr;
            // interior form: z = 288-2s >= zthr  <=>  s <= (288-zthr)/2
            int d = 288 - zthr;
            g_sthr2[t] = (d < 0) ? -1 : (d >> 1);
        }
        __syncthreads();
        // conv3 LUT: tab3[c][p] = prelu_a3(bn3(32-2p)), p in [0,32].
        float a3 = a3p[0];
        for (int idx = tid; idx < CC * 33; idx += 256) {
            int c = idx / 33, p = idx - c * 33;
            float inv = __fdiv_rn(g3[c], __fsqrt_rn(__fadd_rn(v3[c], 1e-5f)));
            float bb  = __fadd_rn(b3[c], -__fmul_rn(m3[c], inv));
            float v = __fadd_rn(__fmul_rn((float)(32 - 2 * p), inv), bb);
            v = (v >= 0.f) ? v : a3 * v;
            g_tab3[idx] = v;
        }
    }
}

// ---------------------------------------------------------------------------
// Kernel A: conv1 (1x1, 128->32) + bn + sign -> packed h1 bitmask per pixel.
// Sign via integer threshold: bit <=> pc <= pthr1[oc].
// ---------------------------------------------------------------------------
__global__ void __launch_bounds__(256) k_conv1(const float* __restrict__ x)
{
    __shared__ uint32_t sw1[CI][4];
    __shared__ int spthr[CI];
    int tid = threadIdx.x;
    if (tid < CI) {
        spthr[tid] = g_pthr1[tid];
        #pragma unroll
        for (int j = 0; j < 4; j++) sw1[tid][j] = g_w1m[tid][j];
    }
    __syncthreads();

    int px = blockIdx.x * 256 + tid;     // 0 .. B*H*W-1 (exact multiple)
    int b  = px / HW;
    int p  = px - b * HW;
    const float* xp = x + (size_t)b * (CC * HW) + p;

    uint32_t s0 = 0, s1 = 0, s2 = 0, s3 = 0;
    #pragma unroll
    for (int i = 0; i < 32; i++) {
        if (xp[(i      ) * HW] > 0.f) s0 |= (1u << i);
        if (xp[(i +  32) * HW] > 0.f) s1 |= (1u << i);
        if (xp[(i +  64) * HW] > 0.f) s2 |= (1u << i);
        if (xp[(i +  96) * HW] > 0.f) s3 |= (1u << i);
    }

    uint32_t outm = 0;
    #pragma unroll
    for (int oc = 0; oc < CI; oc++) {
        int pc = __popc(s0 ^ sw1[oc][0]) + __popc(s1 ^ sw1[oc][1])
               + __popc(s2 ^ sw1[oc][2]) + __popc(s3 ^ sw1[oc][3]);
        if (pc <= spthr[oc]) outm |= (1u << oc);
    }
    g_h1b[px] = outm;
}

// ---------------------------------------------------------------------------
// Kernel B: conv2 (3x3, zero-pad AFTER binarize; sign via integer threshold)
//           + conv3 via LUT + residual + prelu. Tile 32(W) x 8(H), 1 px/thr.
// ---------------------------------------------------------------------------
#define TW 32
#define TH 8

__global__ void __launch_bounds__(256) k_main(
    const float* __restrict__ x, float* __restrict__ out,
    const float* __restrict__ aoutp)
{
    __shared__ uint32_t sh1[TH + 2][TW + 2];
    __shared__ uint32_t sw2[CI][9];
    __shared__ int ssthr2[CI], szthr2[CI];
    __shared__ uint32_t sw3[CC];
    __shared__ float stab[CC * 33];

    int tid = threadIdx.x;
    int tx = tid & (TW - 1);
    int ty = tid / TW;
    int w0 = blockIdx.x * TW;
    int h0 = blockIdx.y * TH;
    int b  = blockIdx.z;

    if (tid < CC) sw3[tid] = g_w3m[tid];
    if (tid < CI) {
        ssthr2[tid] = g_sthr2[tid]; szthr2[tid] = g_zthr2[tid];
        #pragma unroll
        for (int t9 = 0; t9 < 9; t9++) sw2[tid][t9] = g_w2m[tid][t9];
    }
    for (int i = tid; i < CC * 33; i += 256) stab[i] = g_tab3[i];

    const bool border = (w0 == 0) | (h0 == 0) | (w0 + TW == WW) | (h0 + TH == HH);

    // Load h1 bitmask tile + 1-pixel halo
    const uint32_t* h1b = g_h1b + (size_t)b * HW;
    for (int it = tid; it < (TH + 2) * (TW + 2); it += 256) {
        int hy = it / (TW + 2), hx = it - hy * (TW + 2);
        int gh = h0 + hy - 1, gw = w0 + hx - 1;
        uint32_t v = 0;
        if (gh >= 0 && gh < HH && gw >= 0 && gw < WW) v = h1b[gh * WW + gw];
        sh1[hy][hx] = v;
    }
    __syncthreads();

    int gh = h0 + ty, gw = w0 + tx;

    // conv2 neighborhood: center at sh1[ty+1][tx+1]; tap t offset
    // (t/3-1, t%3-1) -> gather sh1[ty + t/3][tx + t%3].
    uint32_t n[9];
    #pragma unroll
    for (int t = 0; t < 9; t++)
        n[t] = sh1[ty + t / 3][tx + t % 3];

    uint32_t h2b = 0;
    if (!border) {
        // Interior: bit <=> sum(popc) <= sthr2[oc]
        #pragma unroll
        for (int oc = 0; oc < CI; oc++) {
            int pc = 0;
            #pragma unroll
            for (int t = 0; t < 9; t++) pc += __popc(n[t] ^ sw2[oc][t]);
            if (pc <= ssthr2[oc]) h2b |= (1u << oc);
        }
    } else {
        bool ok[9];
        #pragma unroll
        for (int t = 0; t < 9; t++) {
            int yy = gh + t / 3 - 1, xx = gw + t % 3 - 1;
            ok[t] = (yy >= 0) & (yy < HH) & (xx >= 0) & (xx < WW);
        }
        #pragma unroll
        for (int oc = 0; oc < CI; oc++) {
            int z = 0;
            #pragma unroll
            for (int t = 0; t < 9; t++) {
                int c9 = 32 - 2 * __popc(n[t] ^ sw2[oc][t]);
                z += ok[t] ? c9 : 0;
            }
            if (z >= szthr2[oc]) h2b |= (1u << oc);
        }
    }

    // conv3 via LUT + residual + prelu
    float aout = aoutp[0];
    size_t base = (size_t)b * (CC * HW) + (size_t)gh * WW + gw;
    const float* xp = x + base;
    float* op = out + base;

    #pragma unroll 16
    for (int c = 0; c < CC; c++) {
        int p = __popc(h2b ^ sw3[c]);
        float v = stab[c * 33 + p];
        float s = v + xp[(size_t)c * HW];
        s = (s >= 0.f) ? s : aout * s;
        __stwt(op + (size_t)c * HW, s);
    }
}

// ---------------------------------------------------------------------------
extern "C" void kernel_launch(void* const* d_in, const int* in_sizes, int n_in,
                              void* d_out, int out_size)
{
    const float* x  = (const float*)d_in[0];
    const float* w1 = (const float*)d_in[1];
    const float* g1 = (const float*)d_in[2];
    const float* b1 = (const float*)d_in[3];
    const float* m1 = (const float*)d_in[4];
    const float* v1 = (const float*)d_in[5];
    // d_in[6] = a1 (unused: prelu with a>0 never changes the following sign)
    const float* w2 = (const float*)d_in[7];
    const float* g2 = (const float*)d_in[8];
    const float* b2 = (const float*)d_in[9];
    const float* m2 = (const float*)d_in[10];
    const float* v2 = (const float*)d_in[11];
    // d_in[12] = a2 (unused, same reason)
    const float* w3 = (const float*)d_in[13];
    const float* g3 = (const float*)d_in[14];
    const float* b3 = (const float*)d_in[15];
    const float* m3 = (const float*)d_in[16];
    const float* v3 = (const float*)d_in[17];
    const float* a3 = (const float*)d_in[18];
    const float* ao = (const float*)d_in[19];
    float* out = (float*)d_out;

    prep_kernel<<<68, 256>>>(w1, g1, b1, m1, v1,
                             w2, g2, b2, m2, v2,
                             w3, g3, b3, m3, v3, a3);

    k_conv1<<<(BB * HW) / 256, 256>>>(x);

    dim3 grid(WW / TW, HH / TH, BB);   // 8 x 16 x 8 = 1024 blocks
    k_main<<<grid, 256>>>(x, out, ao);
}

// round 17
// speedup vs baseline: 1.1218x; 1.1218x over previous
#include <cuda_runtime.h>
#include <stdint.h>

#define CC   128
#define CI   32
#define HH   128
#define WW   256
#define BB   8
#define HW   (HH*WW)

// Precomputed parameters (filled by prep kernel each launch; deterministic).
__device__ uint32_t g_w1m[CI][4];
__device__ int      g_pthr1[CI];        // conv1: bit set  <=>  pc <= pthr1
__device__ uint32_t g_w2m[CI][9];
__device__ int      g_sthr2[CI];        // conv2 interior: bit <=> popc-sum <= sthr2
__device__ int      g_zthr2[CI];        // conv2 border:   bit <=> z >= zthr2
__device__ uint32_t g_w3m[CC];
__device__ float    g_inv3[CC], g_bb3[CC];

// Scratch: h1 binarized activations, 32 channels packed per pixel. 1 MB.
__device__ uint32_t g_h1b[BB * HW];

// ---------------------------------------------------------------------------
// Prep: one mask word per warp (544 words over 68 blocks x 8 warps).
// Block 0 also computes integer thresholds WARP-PARALLEL via the
// prefix/suffix-count trick: bn(z) weakly monotone (inv>0) => positives form
// a prefix in pc (conv1) / suffix in z (conv2); thr = count(positives)-1.
// Each candidate evaluated with the exact reference float ops.
// ---------------------------------------------------------------------------
__global__ void __launch_bounds__(256) prep_kernel(
    const float* __restrict__ w1, const float* __restrict__ g1,
    const float* __restrict__ b1, const float* __restrict__ m1, const float* __restrict__ v1,
    const float* __restrict__ w2, const float* __restrict__ g2,
    const float* __restrict__ b2, const float* __restrict__ m2, const float* __restrict__ v2,
    const float* __restrict__ w3, const float* __restrict__ g3,
    const float* __restrict__ b3, const float* __restrict__ m3, const float* __restrict__ v3)
{
    int tid  = threadIdx.x;
    int lane = tid & 31;
    int warp = tid >> 5;
    int gw   = blockIdx.x * 8 + warp;   // global word id 0..543

    if (gw < 128) {
        int oc = gw >> 2, j = gw & 3;
        uint32_t m = __ballot_sync(0xffffffffu, w1[oc * CC + j * 32 + lane] > 0.f);
        if (lane == 0) g_w1m[oc][j] = m;
    } else if (gw < 416) {
        int idx = gw - 128;
        int oc = idx / 9, t9 = idx - oc * 9;
        uint32_t m = __ballot_sync(0xffffffffu, w2[oc * (CI * 9) + lane * 9 + t9] > 0.f);
        if (lane == 0) g_w2m[oc][t9] = m;
    } else if (gw < 544) {
        int c = gw - 416;
        uint32_t m = __ballot_sync(0xffffffffu, w3[c * CI + lane] > 0.f);
        if (lane == 0) g_w3m[c] = m;
    }

    if (blockIdx.x == 0) {
        // conv1 thresholds: 4 channels per warp, 129 candidates via 5 ballots.
        #pragma unroll
        for (int q = 0; q < 4; q++) {
            int oc = warp * 4 + q;
            float inv = __fdiv_rn(g1[oc], __fsqrt_rn(__fadd_rn(v1[oc], 1e-5f)));
            float bb  = __fadd_rn(b1[oc], -__fmul_rn(m1[oc], inv));
            int cnt = 0;
            #pragma unroll
            for (int k = 0; k < 5; k++) {
                int pc = lane + k * 32;
                bool pos = false;
                if (pc <= 128) {
                    float v = __fadd_rn(__fmul_rn((float)(128 - 2 * pc), inv), bb);
                    pos = v > 0.f;
                }
                cnt += __popc(__ballot_sync(0xffffffffu, pos));
            }
            if (lane == 0) g_pthr1[oc] = cnt - 1;   // prefix: last positive pc
        }
        // conv2 thresholds: 577 candidates (z in [-288,288]) via 19 ballots.
        #pragma unroll
        for (int q = 0; q < 4; q++) {
            int oc = warp * 4 + q;
            float inv = __fdiv_rn(g2[oc], __fsqrt_rn(__fadd_rn(v2[oc], 1e-5f)));
            float bb  = __fadd_rn(b2[oc], -__fmul_rn(m2[oc], inv));
            int cnt = 0;
            #pragma unroll
            for (int k = 0; k < 19; k++) {
                int z = -288 + lane + k * 32;
                bool pos = false;
                if (z <= 288) {
                    float v = __fadd_rn(__fmul_rn((float)z, inv), bb);
                    pos = v > 0.f;
                }
                cnt += __popc(__ballot_sync(0xffffffffu, pos));
            }
            if (lane == 0) {
                int zthr = 289 - cnt;               // suffix: first positive z
                g_zthr2[oc] = zthr;
                int d = 288 - zthr;                 // z=288-2s >= zthr <=> s <= d/2
                g_sthr2[oc] = (d < 0) ? -1 : (d >> 1);
            }
        }
        // conv3 bn constants (float epilogue in k_main).
        if (tid < CC) {
            float inv = __fdiv_rn(g3[tid], __fsqrt_rn(__fadd_rn(v3[tid], 1e-5f)));
            g_inv3[tid] = inv;
            g_bb3[tid]  = __fadd_rn(b3[tid], -__fmul_rn(m3[tid], inv));
        }
    }
}

// ---------------------------------------------------------------------------
// Kernel A: conv1 (1x1, 128->32) + bn + sign -> packed h1 bitmask per pixel.
// Sign via integer threshold: bit <=> pc <= pthr1[oc].
// ---------------------------------------------------------------------------
__global__ void __launch_bounds__(256) k_conv1(const float* __restrict__ x)
{
    __shared__ uint32_t sw1[CI][4];
    __shared__ int spthr[CI];
    int tid = threadIdx.x;
    if (tid < CI) {
        spthr[tid] = g_pthr1[tid];
        #pragma unroll
        for (int j = 0; j < 4; j++) sw1[tid][j] = g_w1m[tid][j];
    }
    __syncthreads();

    int px = blockIdx.x * 256 + tid;     // 0 .. B*H*W-1 (exact multiple)
    int b  = px / HW;
    int p  = px - b * HW;
    const float* xp = x + (size_t)b * (CC * HW) + p;

    uint32_t s0 = 0, s1 = 0, s2 = 0, s3 = 0;
    #pragma unroll
    for (int i = 0; i < 32; i++) {
        if (xp[(i      ) * HW] > 0.f) s0 |= (1u << i);
        if (xp[(i +  32) * HW] > 0.f) s1 |= (1u << i);
        if (xp[(i +  64) * HW] > 0.f) s2 |= (1u << i);
        if (xp[(i +  96) * HW] > 0.f) s3 |= (1u << i);
    }

    uint32_t outm = 0;
    #pragma unroll
    for (int oc = 0; oc < CI; oc++) {
        int pc = __popc(s0 ^ sw1[oc][0]) + __popc(s1 ^ sw1[oc][1])
               + __popc(s2 ^ sw1[oc][2]) + __popc(s3 ^ sw1[oc][3]);
        if (pc <= spthr[oc]) outm |= (1u << oc);
    }
    g_h1b[px] = outm;
}

// ---------------------------------------------------------------------------
// Kernel B: conv2 (3x3, zero-pad AFTER binarize; sign via integer threshold)
//           + conv3 (float FMA epilogue) + residual + prelu.
// Tile 32(W) x 8(H), 1 px/thread (R9 structure).
// ---------------------------------------------------------------------------
#define TW 32
#define TH 8

__global__ void __launch_bounds__(256) k_main(
    const float* __restrict__ x, float* __restrict__ out,
    const float* __restrict__ a3p, const float* __restrict__ aoutp)
{
    __shared__ uint32_t sh1[TH + 2][TW + 2];
    __shared__ uint32_t sw2[CI][9];
    __shared__ int ssthr2[CI], szthr2[CI];
    __shared__ uint32_t sw3[CC];
    __shared__ float sinv3[CC], sbb3[CC];

    int tid = threadIdx.x;
    int tx = tid & (TW - 1);
    int ty = tid / TW;
    int w0 = blockIdx.x * TW;
    int h0 = blockIdx.y * TH;
    int b  = blockIdx.z;

    if (tid < CC) { sw3[tid] = g_w3m[tid]; sinv3[tid] = g_inv3[tid]; sbb3[tid] = g_bb3[tid]; }
    if (tid < CI) {
        ssthr2[tid] = g_sthr2[tid]; szthr2[tid] = g_zthr2[tid];
        #pragma unroll
        for (int t9 = 0; t9 < 9; t9++) sw2[tid][t9] = g_w2m[tid][t9];
    }

    const bool border = (w0 == 0) | (h0 == 0) | (w0 + TW == WW) | (h0 + TH == HH);

    // Load h1 bitmask tile + 1-pixel halo
    const uint32_t* h1b = g_h1b + (size_t)b * HW;
    for (int it = tid; it < (TH + 2) * (TW + 2); it += 256) {
        int hy = it / (TW + 2), hx = it - hy * (TW + 2);
        int gh = h0 + hy - 1, gw = w0 + hx - 1;
        uint32_t v = 0;
        if (gh >= 0 && gh < HH && gw >= 0 && gw < WW) v = h1b[gh * WW + gw];
        sh1[hy][hx] = v;
    }
    __syncthreads();

    int gh = h0 + ty, gw = w0 + tx;

    // conv2 neighborhood: center at sh1[ty+1][tx+1]; tap t offset
    // (t/3-1, t%3-1) -> gather sh1[ty + t/3][tx + t%3].
    uint32_t n[9];
    #pragma unroll
    for (int t = 0; t < 9; t++)
        n[t] = sh1[ty + t / 3][tx + t % 3];

    uint32_t h2b = 0;
    if (!border) {
        // Interior: bit <=> sum(popc) <= sthr2[oc]
        #pragma unroll
        for (int oc = 0; oc < CI; oc++) {
            int pc = 0;
            #pragma unroll
            for (int t = 0; t < 9; t++) pc += __popc(n[t] ^ sw2[oc][t]);
            if (pc <= ssthr2[oc]) h2b |= (1u << oc);
        }
    } else {
        bool ok[9];
        #pragma unroll
        for (int t = 0; t < 9; t++) {
            int yy = gh + t / 3 - 1, xx = gw + t % 3 - 1;
            ok[t] = (yy >= 0) & (yy < HH) & (xx >= 0) & (xx < WW);
        }
        #pragma unroll
        for (int oc = 0; oc < CI; oc++) {
            int z = 0;
            #pragma unroll
            for (int t = 0; t < 9; t++) {
                int c9 = 32 - 2 * __popc(n[t] ^ sw2[oc][t]);
                z += ok[t] ? c9 : 0;
            }
            if (z >= szthr2[oc]) h2b |= (1u << oc);
        }
    }

    // conv3 + bn + prelu + residual + prelu (float FMA epilogue, no LUT)
    float a3   = a3p[0];
    float aout = aoutp[0];
    size_t base = (size_t)b * (CC * HW) + (size_t)gh * WW + gw;
    const float* xp = x + base;
    float* op = out + base;

    #pragma unroll 16
    for (int c = 0; c < CC; c++) {
        int z = 32 - 2 * __popc(h2b ^ sw3[c]);
        float v = __fadd_rn(__fmul_rn((float)z, sinv3[c]), sbb3[c]);
        v = (v >= 0.f) ? v : a3 * v;
        float s = v + xp[(size_t)c * HW];
        s = (s >= 0.f) ? s : aout * s;
        __stwt(op + (size_t)c * HW, s);
    }
}

// ---------------------------------------------------------------------------
extern "C" void kernel_launch(void* const* d_in, const int* in_sizes, int n_in,
                              void* d_out, int out_size)
{
    const float* x  = (const float*)d_in[0];
    const float* w1 = (const float*)d_in[1];
    const float* g1 = (const float*)d_in[2];
    const float* b1 = (const float*)d_in[3];
    const float* m1 = (const float*)d_in[4];
    const float* v1 = (const float*)d_in[5];
    // d_in[6] = a1 (unused: prelu with a>0 never changes the following sign)
    const float* w2 = (const float*)d_in[7];
    const float* g2 = (const float*)d_in[8];
    const float* b2 = (const float*)d_in[9];
    const float* m2 = (const float*)d_in[10];
    const float* v2 = (const float*)d_in[11];
    // d_in[12] = a2 (unused, same reason)
    const float* w3 = (const float*)d_in[13];
    const float* g3 = (const float*)d_in[14];
    const float* b3 = (const float*)d_in[15];
    const float* m3 = (const float*)d_in[16];
    const float* v3 = (const float*)d_in[17];
    const float* a3 = (const float*)d_in[18];
    const float* ao = (const float*)d_in[19];
    float* out = (float*)d_out;

    prep_kernel<<<68, 256>>>(w1, g1, b1, m1, v1,
                             w2, g2, b2, m2, v2,
                             w3, g3, b3, m3, v3);

    k_conv1<<<(BB * HW) / 256, 256>>>(x);

    dim3 grid(WW / TW, HH / TH, BB);   // 8 x 16 x 8 = 1024 blocks
    k_main<<<grid, 256>>>(x, out, a3, ao);
}